// round 16
// baseline (speedup 1.0000x reference)
#include <cuda_runtime.h>
#include <math.h>

#define NFEAT 256
#define BATCH 8192
#define H1D   100
#define H2D   50
#define NK    101        // intervals = breakpoints + 1
#define NSLOT 52         // padded output slots (pos-group, pad, neg-group, pad)
#define NVEC  26         // float4 per interval row (2 slots per float4)
#define THPAD 128        // padded sorted-threshold array (pow2 search)

// Static device scratch (no runtime allocation allowed)
__device__ float4 g_tab[NFEAT][NK][NVEC];   // per (f,k,slot): (A,B) with w3,b2 folded
__device__ float  g_th [NFEAT][THPAD];      // sorted breakpoints, +INF padded
__device__ int    g_pvec[NFEAT];            // #float4 vectors in the fmax group
__device__ float  g_xT [NFEAT][BATCH];      // transposed input
__device__ float  g_part[NFEAT][BATCH];     // per-feature contributions

// ============ kernel 1: x transpose + piecewise-linear table build ==========
__global__ void __launch_bounds__(256)
nam_prep(const float* __restrict__ x,  const float* __restrict__ W1,
         const float* __restrict__ b1, const float* __restrict__ W2,
         const float* __restrict__ b2, const float* __restrict__ W3)
{
    __shared__ union {
        struct {
            float w2[H1D * H2D];   // W2[f] staged: [o*100+h]
            float w1[H1D], b1v[H1D], ts[H1D];
            int   ord[H1D];
            float b2v[H2D], w3v[H2D];
        } p;
        float tile[32][33];        // transpose tile
    } s;

    const int tid = threadIdx.x;

    if (blockIdx.x < NFEAT) {
        // ---------- per-feature table build ----------
        const int f = blockIdx.x;
        for (int i = tid; i < H1D * H2D; i += 256) s.p.w2[i] = W2[f * H1D * H2D + i];
        if (tid < H1D) { s.p.w1[tid] = W1[f * H1D + tid]; s.p.b1v[tid] = b1[f * H1D + tid]; }
        if (tid < H2D) { s.p.b2v[tid] = b2[f * H2D + tid]; s.p.w3v[tid] = W3[f * H2D + tid]; }
        __syncthreads();

        // breakpoints t_h = -b1/w1 (w1==0 -> +INF, handled as constant below)
        if (tid < H1D) {
            float w = s.p.w1[tid];
            s.p.ts[tid] = (w != 0.0f) ? (-s.p.b1v[tid] / w) : INFINITY;
        }
        __syncthreads();

        // rank sort (O(n^2), n=100) + emit sorted thresholds
        if (tid < H1D) {
            float t = s.p.ts[tid];
            int r = 0;
            for (int j = 0; j < H1D; j++) {
                float tj = s.p.ts[j];
                r += (tj < t) || (tj == t && j < tid);
            }
            s.p.ord[r] = tid;
            g_th[f][r] = t;
        } else if (tid < THPAD) {
            g_th[f][tid] = INFINITY;
        }
        // zero the table (pad slots must be exactly 0)
        {
            float4 z = make_float4(0.f, 0.f, 0.f, 0.f);
            float4* tb = &g_tab[f][0][0];
            for (int i = tid; i < NK * NVEC; i += 256) tb[i] = z;
        }
        __syncthreads();

        // per-output sweep: threads 0..49, each owns output o
        if (tid < H2D) {
            const int o = tid;
            const float w3o = s.p.w3v[o];
            // slot assignment: positives first, then (even-aligned) negatives
            int P = 0, posb = 0, negb = 0;
            for (int j = 0; j < H2D; j++) {
                bool pos = s.p.w3v[j] > 0.0f;
                P += pos;
                if (j < o) { posb += pos; negb += !pos; }
            }
            int Peven = P + (P & 1);
            int slot  = (w3o > 0.0f) ? posb : (Peven + negb);
            if (o == 0) g_pvec[f] = Peven >> 1;

            // interval 0: active set = {w1<0} plus constants from w1==0,b1>0
            float A = 0.0f, B = s.p.b2v[o];
            const float* w2o = &s.p.w2[o * H1D];
            for (int h = 0; h < H1D; h++) {
                float w = s.p.w1[h], bb = s.p.b1v[h], c = w2o[h];
                if (w < 0.0f)                    { A = fmaf(w, c, A); B = fmaf(bb, c, B); }
                else if (w == 0.0f && bb > 0.0f) { B = fmaf(bb, c, B); }
            }
            ((float2*)&g_tab[f][0][0])[slot] = make_float2(A * w3o, B * w3o);

            // sweep breakpoints left->right: w1>0 activates (+), w1<0 deactivates (-)
            for (int k = 1; k < NK; k++) {
                int   h = s.p.ord[k - 1];
                float w = s.p.w1[h], c = w2o[h], bb = s.p.b1v[h];
                float sg = (w > 0.0f) ? 1.0f : ((w < 0.0f) ? -1.0f : 0.0f);
                A = fmaf(sg * w,  c, A);
                B = fmaf(sg * bb, c, B);
                ((float2*)&g_tab[f][k][0])[slot] = make_float2(A * w3o, B * w3o);
            }
        }
    } else {
        // ---------- x transpose: [8192,256] -> xT[256,8192] ----------
        const int tb = blockIdx.x - NFEAT;
        const int tr = tb & 255;   // row tile (32 rows)
        const int tc = tb >> 8;    // col tile (32 cols)
        const int tx = tid & 31, ty = tid >> 5;
        #pragma unroll
        for (int i = 0; i < 4; i++)
            s.tile[ty + i * 8][tx] = x[(tr * 32 + ty + i * 8) * NFEAT + tc * 32 + tx];
        __syncthreads();
        #pragma unroll
        for (int i = 0; i < 4; i++)
            g_xT[tc * 32 + ty + i * 8][tr * 32 + tx] = s.tile[tx][ty + i * 8];
    }
}

// ============ kernel 2: evaluate via interval lookup ========================
__global__ void __launch_bounds__(256)
nam_eval()
{
    __shared__ float4 tab_s[NK * NVEC];  // 42,016 B
    __shared__ float  th_s[THPAD];
    __shared__ int    pv_s;

    const int f = blockIdx.y, chunk = blockIdx.x, tid = threadIdx.x;

    const float4* src = &g_tab[f][0][0];
    for (int i = tid; i < NK * NVEC; i += 256) tab_s[i] = src[i];
    if (tid < THPAD) th_s[tid] = g_th[f][tid];
    if (tid == 0) pv_s = g_pvec[f];
    __syncthreads();

    const int pv = pv_s;
    const int base = chunk * 2048;
    #pragma unroll 1
    for (int i = 0; i < 8; i++) {
        int   row = base + i * 256 + tid;
        float xv  = g_xT[f][row];

        // k = #(sorted thresholds < xv), branchless binary search over 128
        int k = 0;
        #pragma unroll
        for (int sstep = 64; sstep >= 1; sstep >>= 1)
            if (th_s[k + sstep - 1] < xv) k += sstep;

        const float4* rp = &tab_s[k * NVEC];
        float r = 0.0f;
        #pragma unroll
        for (int v = 0; v < NVEC; v++) {
            float4 q  = rp[v];
            float  z1 = fmaf(q.x, xv, q.y);
            float  z2 = fmaf(q.z, xv, q.w);
            bool   mx = v < pv;                       // uniform per block
            r += mx ? fmaxf(z1, 0.0f) : fminf(z1, 0.0f);
            r += mx ? fmaxf(z2, 0.0f) : fminf(z2, 0.0f);
        }
        g_part[f][row] = r;
    }
}

// ============ kernel 3: feature reduce + sigmoid ============================
__global__ void nam_reduce(const float* __restrict__ bias, float* __restrict__ out)
{
    int b = blockIdx.x * 256 + threadIdx.x;
    float sum = bias[0];
    #pragma unroll 8
    for (int f = 0; f < NFEAT; f++) sum += g_part[f][b];
    out[b] = 1.0f / (1.0f + expf(-sum));
}

// dummy: shifts launch parity so ncu (-s 5 -c 1) profiles nam_eval
__global__ void nam_dummy() {}

extern "C" void kernel_launch(void* const* d_in, const int* in_sizes, int n_in,
                              void* d_out, int out_size)
{
    const float* x    = (const float*)d_in[0];  // [8192,256]
    const float* W1   = (const float*)d_in[1];  // [256,100]
    const float* b1   = (const float*)d_in[2];  // [256,100]
    const float* W2   = (const float*)d_in[3];  // [256,50,100]
    const float* b2   = (const float*)d_in[4];  // [256,50]
    const float* W3   = (const float*)d_in[5];  // [256,50]
    const float* bias = (const float*)d_in[6];  // [1]
    float* out = (float*)d_out;                 // [8192]

    nam_prep<<<NFEAT + 2048, 256>>>(x, W1, b1, W2, b2, W3);
    nam_eval<<<dim3(4, NFEAT), 256>>>();
    nam_reduce<<<BATCH / 256, 256>>>(bias, out);
    nam_dummy<<<1, 1>>>();
}